// round 3
// baseline (speedup 1.0000x reference)
#include <cuda_runtime.h>
#include <cuda_bf16.h>

#define N_NODES 50000
#define N_EDGES 600000
#define DIM 128
#define EPS 1e-5f
#define N_SBLOCKS ((N_NODES + 1023) / 1024)   // 49

// ---------------- scratch (device globals; no allocation allowed) ----------------
__device__ __align__(16) float g_s[N_NODES * DIM];
__device__ __align__(16) float g_h[N_NODES * DIM];
__device__ int   g_cnt[N_NODES];
__device__ int   g_rowptr[N_NODES + 1];
__device__ int   g_cursor[N_NODES];
__device__ int2  g_epack[N_EDGES];
__device__ int   g_bsums[N_SBLOCKS + 1];

// ---------------- CSR build ----------------
__global__ void hist_kernel(const int* __restrict__ tgt, int* __restrict__ cnt, int e)
{
    int i = blockIdx.x * blockDim.x + threadIdx.x;
    if (i < e) atomicAdd(&cnt[tgt[i]], 1);
}

// phase 1: per-block (1024-wide) exclusive scan, write local prefix + block sum
__global__ __launch_bounds__(1024) void scan1_kernel(
    const int* __restrict__ cnt, int* __restrict__ rowptr, int* __restrict__ bsums, int n)
{
    __shared__ int wsum[32];
    int tid  = threadIdx.x;
    int lane = tid & 31;
    int wid  = tid >> 5;
    int i    = blockIdx.x * 1024 + tid;
    int v = (i < n) ? cnt[i] : 0;

    int x = v;
    #pragma unroll
    for (int off = 1; off < 32; off <<= 1) {
        int y = __shfl_up_sync(0xffffffffu, x, off);
        if (lane >= off) x += y;
    }
    if (lane == 31) wsum[wid] = x;
    __syncthreads();
    if (wid == 0) {
        int ws = wsum[lane];
        #pragma unroll
        for (int off = 1; off < 32; off <<= 1) {
            int y = __shfl_up_sync(0xffffffffu, ws, off);
            if (lane >= off) ws += y;
        }
        wsum[lane] = ws;
    }
    __syncthreads();
    int excl = x - v + (wid ? wsum[wid - 1] : 0);
    if (i < n) rowptr[i] = excl;
    if (tid == 0) bsums[blockIdx.x] = wsum[31];
}

// phase 2: scan the (<=64) block sums in one 64-thread block
__global__ void scan2_kernel(int* __restrict__ bsums, int nb)
{
    __shared__ int w2[2];
    int tid  = threadIdx.x;
    int lane = tid & 31;
    int wid  = tid >> 5;
    int v = (tid < nb) ? bsums[tid] : 0;
    int x = v;
    #pragma unroll
    for (int off = 1; off < 32; off <<= 1) {
        int y = __shfl_up_sync(0xffffffffu, x, off);
        if (lane >= off) x += y;
    }
    if (lane == 31) w2[wid] = x;
    __syncthreads();
    int incl = x + (wid ? w2[0] : 0);
    if (tid < nb) bsums[tid] = incl - v;           // exclusive block offset
    if (tid == 63) bsums[nb] = incl;               // grand total
}

// phase 3: add block offsets, init cursor, write rowptr[n]
__global__ __launch_bounds__(1024) void scan3_kernel(
    int* __restrict__ rowptr, int* __restrict__ cursor,
    const int* __restrict__ bsums, int n, int nb)
{
    int i = blockIdx.x * 1024 + threadIdx.x;
    if (i < n) {
        int r = rowptr[i] + bsums[blockIdx.x];
        rowptr[i] = r;
        cursor[i] = r;
    }
    if (i == 0) rowptr[n] = bsums[nb];
}

__global__ void scatter_kernel(const int* __restrict__ src, const int* __restrict__ tgt,
                               const float* __restrict__ ew, int* __restrict__ cursor,
                               int2* __restrict__ epack, int e)
{
    int i = blockIdx.x * blockDim.x + threadIdx.x;
    if (i < e) {
        int t = tgt[i];
        int pos = atomicAdd(&cursor[t], 1);
        epack[pos] = make_int2(src[i], __float_as_int(ew[i]));
    }
}

// ---------------- GEMM: S[n,128] = X[n,128] @ Wsub[128,128] + (b + t*Wrow0) ----------------
// 128x128 block tile, BK=16, 8x8 per thread, double-buffered smem.
#define GBM 128
#define GBK 16
#define NKT (DIM / GBK)   // 8 k-tiles

__global__ __launch_bounds__(256, 2) void gemm_kernel(
    const float* __restrict__ X, const float* __restrict__ Wsub,
    const float* __restrict__ Wrow0, const float* __restrict__ bvec,
    const float* __restrict__ tptr, float* __restrict__ S, int n)
{
    __shared__ float xs[2][GBK][GBM];   // transposed: [k][row]
    __shared__ float ws[2][GBK][DIM];

    int tid = threadIdx.x;
    int block_row = blockIdx.x * GBM;

    // X tile load mapping: 512 float4 -> 2 per thread
    int xr0 = tid >> 2;            // row 0..63 (p adds 64)
    int xc0 = (tid & 3) * 4;       // col within k-tile
    // W tile load mapping: 512 float4 -> 2 per thread
    int wk0 = tid >> 5;            // k 0..7 (p adds 8)
    int wc0 = (tid & 31) * 4;

    // compute mapping
    int tx = tid & 15, ty = tid >> 4;
    int c0 = tx * 4, c1 = c0 + 64;
    int r0 = ty * 4, r1 = r0 + 64;

    float4 acc[2][2][4];
    #pragma unroll
    for (int a = 0; a < 2; a++)
        #pragma unroll
        for (int bq = 0; bq < 2; bq++)
            #pragma unroll
            for (int i = 0; i < 4; i++)
                acc[a][bq][i] = make_float4(0.f, 0.f, 0.f, 0.f);

    float4 xv[2], wv[2];

    // preload k-tile 0
    #pragma unroll
    for (int p = 0; p < 2; p++) {
        int grow = block_row + xr0 + p * 64;
        xv[p] = (grow < n) ? *(const float4*)(X + (size_t)grow * DIM + xc0)
                           : make_float4(0.f, 0.f, 0.f, 0.f);
        wv[p] = *(const float4*)(Wsub + (size_t)(wk0 + p * 8) * DIM + wc0);
    }
    #pragma unroll
    for (int p = 0; p < 2; p++) {
        int rr = xr0 + p * 64;
        xs[0][xc0 + 0][rr] = xv[p].x;
        xs[0][xc0 + 1][rr] = xv[p].y;
        xs[0][xc0 + 2][rr] = xv[p].z;
        xs[0][xc0 + 3][rr] = xv[p].w;
        *(float4*)&ws[0][wk0 + p * 8][wc0] = wv[p];
    }
    __syncthreads();

    #pragma unroll
    for (int t = 0; t < NKT; t++) {
        int buf = t & 1;
        if (t < NKT - 1) {
            int k0 = (t + 1) * GBK;
            #pragma unroll
            for (int p = 0; p < 2; p++) {
                int grow = block_row + xr0 + p * 64;
                xv[p] = (grow < n) ? *(const float4*)(X + (size_t)grow * DIM + k0 + xc0)
                                   : make_float4(0.f, 0.f, 0.f, 0.f);
                wv[p] = *(const float4*)(Wsub + (size_t)(k0 + wk0 + p * 8) * DIM + wc0);
            }
        }
        #pragma unroll
        for (int kk = 0; kk < GBK; kk++) {
            float4 wa = *(const float4*)&ws[buf][kk][c0];
            float4 wb = *(const float4*)&ws[buf][kk][c1];
            float4 xa = *(const float4*)&xs[buf][kk][r0];
            float4 xb = *(const float4*)&xs[buf][kk][r1];
            float xra[4] = {xa.x, xa.y, xa.z, xa.w};
            float xrb[4] = {xb.x, xb.y, xb.z, xb.w};
            #pragma unroll
            for (int i = 0; i < 4; i++) {
                acc[0][0][i].x = fmaf(xra[i], wa.x, acc[0][0][i].x);
                acc[0][0][i].y = fmaf(xra[i], wa.y, acc[0][0][i].y);
                acc[0][0][i].z = fmaf(xra[i], wa.z, acc[0][0][i].z);
                acc[0][0][i].w = fmaf(xra[i], wa.w, acc[0][0][i].w);
                acc[0][1][i].x = fmaf(xra[i], wb.x, acc[0][1][i].x);
                acc[0][1][i].y = fmaf(xra[i], wb.y, acc[0][1][i].y);
                acc[0][1][i].z = fmaf(xra[i], wb.z, acc[0][1][i].z);
                acc[0][1][i].w = fmaf(xra[i], wb.w, acc[0][1][i].w);
                acc[1][0][i].x = fmaf(xrb[i], wa.x, acc[1][0][i].x);
                acc[1][0][i].y = fmaf(xrb[i], wa.y, acc[1][0][i].y);
                acc[1][0][i].z = fmaf(xrb[i], wa.z, acc[1][0][i].z);
                acc[1][0][i].w = fmaf(xrb[i], wa.w, acc[1][0][i].w);
                acc[1][1][i].x = fmaf(xrb[i], wb.x, acc[1][1][i].x);
                acc[1][1][i].y = fmaf(xrb[i], wb.y, acc[1][1][i].y);
                acc[1][1][i].z = fmaf(xrb[i], wb.z, acc[1][1][i].z);
                acc[1][1][i].w = fmaf(xrb[i], wb.w, acc[1][1][i].w);
            }
        }
        if (t < NKT - 1) {
            int nbuf = buf ^ 1;
            #pragma unroll
            for (int p = 0; p < 2; p++) {
                int rr = xr0 + p * 64;
                xs[nbuf][xc0 + 0][rr] = xv[p].x;
                xs[nbuf][xc0 + 1][rr] = xv[p].y;
                xs[nbuf][xc0 + 2][rr] = xv[p].z;
                xs[nbuf][xc0 + 3][rr] = xv[p].w;
                *(float4*)&ws[nbuf][wk0 + p * 8][wc0] = wv[p];
            }
            __syncthreads();
        }
    }

    // epilogue: bias = b + t*Wrow0, store
    float tval = *tptr;
    float4 bb[2];
    {
        float4 b0 = *(const float4*)(bvec + c0);
        float4 w0 = *(const float4*)(Wrow0 + c0);
        bb[0] = make_float4(fmaf(tval, w0.x, b0.x), fmaf(tval, w0.y, b0.y),
                            fmaf(tval, w0.z, b0.z), fmaf(tval, w0.w, b0.w));
        float4 b1 = *(const float4*)(bvec + c1);
        float4 w1 = *(const float4*)(Wrow0 + c1);
        bb[1] = make_float4(fmaf(tval, w1.x, b1.x), fmaf(tval, w1.y, b1.y),
                            fmaf(tval, w1.z, b1.z), fmaf(tval, w1.w, b1.w));
    }
    #pragma unroll
    for (int a = 0; a < 2; a++) {
        int rbase = block_row + (a ? r1 : r0);
        #pragma unroll
        for (int i = 0; i < 4; i++) {
            int grow = rbase + i;
            if (grow < n) {
                #pragma unroll
                for (int bq = 0; bq < 2; bq++) {
                    float4 o;
                    o.x = acc[a][bq][i].x + bb[bq].x;
                    o.y = acc[a][bq][i].y + bb[bq].y;
                    o.z = acc[a][bq][i].z + bb[bq].z;
                    o.w = acc[a][bq][i].w + bb[bq].w;
                    *(float4*)(S + (size_t)grow * DIM + (bq ? c1 : c0)) = o;
                }
            }
        }
    }
}

// ---------------- aggregation + ReLU + GroupNorm (group size 4 == one lane) ----------------
__global__ __launch_bounds__(256) void agg_gn_kernel(
    const float* __restrict__ S, const int* __restrict__ rowptr,
    const int2* __restrict__ epack,
    const float* __restrict__ gamma, const float* __restrict__ beta,
    float* __restrict__ out, int n)
{
    int warp = (blockIdx.x * blockDim.x + threadIdx.x) >> 5;
    int lane = threadIdx.x & 31;
    if (warp >= n) return;

    int beg = rowptr[warp];
    int deg = rowptr[warp + 1] - beg;

    float ax = 0.f, ay = 0.f, az = 0.f, aw = 0.f;

    for (int base = 0; base < deg; base += 32) {
        int m = min(32, deg - base);
        int2 ep = make_int2(0, 0);
        if (base + lane < deg) ep = epack[beg + base + lane];

        int jj = 0;
        for (; jj + 4 <= m; jj += 4) {
            int   s0 = __shfl_sync(0xffffffffu, ep.x, jj + 0);
            int   s1 = __shfl_sync(0xffffffffu, ep.x, jj + 1);
            int   s2 = __shfl_sync(0xffffffffu, ep.x, jj + 2);
            int   s3 = __shfl_sync(0xffffffffu, ep.x, jj + 3);
            float w0 = __int_as_float(__shfl_sync(0xffffffffu, ep.y, jj + 0));
            float w1 = __int_as_float(__shfl_sync(0xffffffffu, ep.y, jj + 1));
            float w2 = __int_as_float(__shfl_sync(0xffffffffu, ep.y, jj + 2));
            float w3 = __int_as_float(__shfl_sync(0xffffffffu, ep.y, jj + 3));
            float4 v0 = *(const float4*)(S + (size_t)s0 * DIM + lane * 4);
            float4 v1 = *(const float4*)(S + (size_t)s1 * DIM + lane * 4);
            float4 v2 = *(const float4*)(S + (size_t)s2 * DIM + lane * 4);
            float4 v3 = *(const float4*)(S + (size_t)s3 * DIM + lane * 4);
            ax = fmaf(w0, v0.x, ax); ay = fmaf(w0, v0.y, ay);
            az = fmaf(w0, v0.z, az); aw = fmaf(w0, v0.w, aw);
            ax = fmaf(w1, v1.x, ax); ay = fmaf(w1, v1.y, ay);
            az = fmaf(w1, v1.z, az); aw = fmaf(w1, v1.w, aw);
            ax = fmaf(w2, v2.x, ax); ay = fmaf(w2, v2.y, ay);
            az = fmaf(w2, v2.z, az); aw = fmaf(w2, v2.w, aw);
            ax = fmaf(w3, v3.x, ax); ay = fmaf(w3, v3.y, ay);
            az = fmaf(w3, v3.z, az); aw = fmaf(w3, v3.w, aw);
        }
        for (; jj < m; jj++) {
            int   s0 = __shfl_sync(0xffffffffu, ep.x, jj);
            float w0 = __int_as_float(__shfl_sync(0xffffffffu, ep.y, jj));
            float4 v0 = *(const float4*)(S + (size_t)s0 * DIM + lane * 4);
            ax = fmaf(w0, v0.x, ax); ay = fmaf(w0, v0.y, ay);
            az = fmaf(w0, v0.z, az); aw = fmaf(w0, v0.w, aw);
        }
    }

    // ReLU
    ax = fmaxf(ax, 0.f); ay = fmaxf(ay, 0.f);
    az = fmaxf(az, 0.f); aw = fmaxf(aw, 0.f);
    // GroupNorm over this lane's 4 channels
    float mu = (ax + ay + az + aw) * 0.25f;
    float d0 = ax - mu, d1 = ay - mu, d2 = az - mu, d3 = aw - mu;
    float var = (d0 * d0 + d1 * d1 + d2 * d2 + d3 * d3) * 0.25f;
    float inv = rsqrtf(var + EPS);
    float4 g = *(const float4*)(gamma + lane * 4);
    float4 b = *(const float4*)(beta  + lane * 4);
    float4 o;
    o.x = fmaf(d0 * inv, g.x, b.x);
    o.y = fmaf(d1 * inv, g.y, b.y);
    o.z = fmaf(d2 * inv, g.z, b.z);
    o.w = fmaf(d3 * inv, g.w, b.w);
    *(float4*)(out + (size_t)warp * DIM + lane * 4) = o;
}

// ---------------- launch ----------------
extern "C" void kernel_launch(void* const* d_in, const int* in_sizes, int n_in,
                              void* d_out, int out_size)
{
    const float* t      = (const float*)d_in[0];
    const float* x      = (const float*)d_in[1];
    const int*   src    = (const int*)  d_in[2];
    const int*   tgt    = (const int*)  d_in[3];
    const float* edge_w = (const float*)d_in[4];
    const float* W1     = (const float*)d_in[5];
    const float* b1     = (const float*)d_in[6];
    const float* W2     = (const float*)d_in[7];
    const float* b2     = (const float*)d_in[8];
    const float* gamma1 = (const float*)d_in[9];
    const float* beta1  = (const float*)d_in[10];
    const float* gamma2 = (const float*)d_in[11];
    const float* beta2  = (const float*)d_in[12];
    float* out = (float*)d_out;

    float* s_buf;  cudaGetSymbolAddress((void**)&s_buf,  g_s);
    float* h_buf;  cudaGetSymbolAddress((void**)&h_buf,  g_h);
    int*   cnt;    cudaGetSymbolAddress((void**)&cnt,    g_cnt);
    int*   rowptr; cudaGetSymbolAddress((void**)&rowptr, g_rowptr);
    int*   cursor; cudaGetSymbolAddress((void**)&cursor, g_cursor);
    int2*  epack;  cudaGetSymbolAddress((void**)&epack,  g_epack);
    int*   bsums;  cudaGetSymbolAddress((void**)&bsums,  g_bsums);

    // ---- CSR build (once; reused by both layers) ----
    cudaMemsetAsync(cnt, 0, N_NODES * sizeof(int));
    hist_kernel<<<(N_EDGES + 255) / 256, 256>>>(tgt, cnt, N_EDGES);
    scan1_kernel<<<N_SBLOCKS, 1024>>>(cnt, rowptr, bsums, N_NODES);
    scan2_kernel<<<1, 64>>>(bsums, N_SBLOCKS);
    scan3_kernel<<<N_SBLOCKS, 1024>>>(rowptr, cursor, bsums, N_NODES, N_SBLOCKS);
    scatter_kernel<<<(N_EDGES + 255) / 256, 256>>>(src, tgt, edge_w, cursor, epack, N_EDGES);

    int gemm_blocks = (N_NODES + GBM - 1) / GBM;
    int agg_blocks  = (N_NODES + 7) / 8;   // 8 warps per 256-thread block

    // ---- layer 1 ----
    gemm_kernel<<<gemm_blocks, 256>>>(x, W1 + DIM, W1, b1, t, s_buf, N_NODES);
    agg_gn_kernel<<<agg_blocks, 256>>>(s_buf, rowptr, epack, gamma1, beta1, h_buf, N_NODES);

    // ---- layer 2 ----
    gemm_kernel<<<gemm_blocks, 256>>>(h_buf, W2 + DIM, W2, b2, t, s_buf, N_NODES);
    agg_gn_kernel<<<agg_blocks, 256>>>(s_buf, rowptr, epack, gamma2, beta2, out, N_NODES);
}

// round 5
// speedup vs baseline: 1.0768x; 1.0768x over previous
#include <cuda_runtime.h>
#include <cuda_bf16.h>
#include <cstdint>

#define N_NODES 50000
#define N_EDGES 600000
#define DIM 128
#define EPS 1e-5f
#define N_SBLOCKS ((N_NODES + 1023) / 1024)   // 49
#define N_TILES ((N_NODES + 127) / 128)       // 391

#if defined(__CUDA_ARCH__) && defined(__CUDA_ARCH_FEAT_SM103_ALL)
#define HAS_TC 1
#else
#define HAS_TC 0
#endif

// ---------------- scratch (device globals; no allocation allowed) ----------------
__device__ __align__(16) float g_s[N_NODES * DIM];
__device__ __align__(16) float g_h[N_NODES * DIM];
__device__ int   g_cnt[N_NODES];
__device__ int   g_rowptr[N_NODES + 1];
__device__ int   g_cursor[N_NODES];
__device__ int2  g_epack[N_EDGES];
__device__ int   g_bsums[N_SBLOCKS + 1];
// pre-swizzled W^T bf16 SMEM images (32KB each) + fused bias, per layer
__device__ __align__(16) char  g_bt_hi[2][32768];
__device__ __align__(16) char  g_bt_lo[2][32768];
__device__ __align__(16) float g_bias[2][DIM];

// blocked-atom SW128 byte offset for [128 rows x 128 bf16 cols]
__host__ __device__ __forceinline__ uint32_t sw_off(int r, int c) {
    uint32_t off = (uint32_t)((r >> 3) + (c >> 6) * 16) * 1024u + (uint32_t)(r & 7) * 128u
                 + (uint32_t)(c & 63) * 2u;
    return off ^ ((off >> 3) & 0x70);
}

// ---------------- PTX helpers (used only under HAS_TC) ----------------
__device__ __forceinline__ uint32_t smem_u32(const void* p) {
    uint32_t a;
    asm("{ .reg .u64 t; cvta.to.shared.u64 t, %1; cvt.u32.u64 %0, t; }" : "=r"(a) : "l"(p));
    return a;
}
#if HAS_TC
__device__ __forceinline__ uint32_t elect_one() {
    uint32_t p;
    asm volatile("{ .reg .pred p; elect.sync _|p, 0xFFFFFFFF; selp.b32 %0, 1, 0, p; }" : "=r"(p));
    return p;
}
#define MBAR_INIT(a, c) asm volatile("mbarrier.init.shared.b64 [%0], %1;" :: "r"(a), "r"(c) : "memory")
#define MBAR_INVAL(a)   asm volatile("mbarrier.inval.shared.b64 [%0];" :: "r"(a) : "memory")
#define MBAR_WAIT(a, ph) do {                                                              \
    uint32_t _m = (a), _p = (ph), _d;                                                      \
    asm volatile("{ .reg .pred p; mbarrier.try_wait.parity.acquire.cta.shared::cta.b64 p, [%1], %2;" \
                 " selp.b32 %0, 1, 0, p; }" : "=r"(_d) : "r"(_m), "r"(_p) : "memory");     \
    if (!_d) {                                                                             \
        asm volatile("{ .reg .pred P1; WL%=: mbarrier.try_wait.parity.acquire.cta.shared::cta.b64 P1, [%0], %1, 0x989680;" \
                     " @P1 bra.uni WD%=; bra.uni WL%=; WD%=: }" :: "r"(_m), "r"(_p) : "memory"); \
    } } while (0)
#define TC_ALLOC(sa, nc)  asm volatile("tcgen05.alloc.cta_group::1.sync.aligned.shared::cta.b32 [%0], %1;" :: "r"(sa), "r"(nc) : "memory")
#define TC_RELINQ()       asm volatile("tcgen05.relinquish_alloc_permit.cta_group::1.sync.aligned;")
#define TC_DEALLOC(t, nc) asm volatile("tcgen05.dealloc.cta_group::1.sync.aligned.b32 %0, %1;" :: "r"(t), "r"(nc))
#define TC_COMMIT(mb)     asm volatile("tcgen05.commit.cta_group::1.mbarrier::arrive::one.shared::cluster.b64 [%0];" :: "r"(mb) : "memory")
#define TC_FENCE_AFTER()  asm volatile("tcgen05.fence::after_thread_sync;" ::: "memory")
#define TC_FENCE_BEFORE() asm volatile("tcgen05.fence::before_thread_sync;" ::: "memory")
#define TC_WAIT_LD()      asm volatile("tcgen05.wait::ld.sync.aligned;" ::: "memory")

__device__ __forceinline__ void tc_mma_f16_ss(uint32_t d, uint64_t ad, uint64_t bd,
                                              uint32_t idesc, uint32_t en) {
    asm volatile("{ .reg .pred p; setp.ne.u32 p, %5, 0;"
                 " tcgen05.mma.cta_group::1.kind::f16 [%0], %1, %2, %3, {%4, %4, %4, %4}, p; }"
                 :: "r"(d), "l"(ad), "l"(bd), "r"(idesc), "r"(0u), "r"(en) : "memory");
}
#define TC_LD_X32(r, ta)                                                                   \
    asm volatile("tcgen05.ld.sync.aligned.32x32b.x32.b32 "                                 \
        "{%0,%1,%2,%3,%4,%5,%6,%7,%8,%9,%10,%11,%12,%13,%14,%15,"                          \
        "%16,%17,%18,%19,%20,%21,%22,%23,%24,%25,%26,%27,%28,%29,%30,%31}, [%32];"         \
        : "=r"((r)[0]),"=r"((r)[1]),"=r"((r)[2]),"=r"((r)[3]),"=r"((r)[4]),"=r"((r)[5]),   \
          "=r"((r)[6]),"=r"((r)[7]),"=r"((r)[8]),"=r"((r)[9]),"=r"((r)[10]),"=r"((r)[11]), \
          "=r"((r)[12]),"=r"((r)[13]),"=r"((r)[14]),"=r"((r)[15]),"=r"((r)[16]),"=r"((r)[17]),\
          "=r"((r)[18]),"=r"((r)[19]),"=r"((r)[20]),"=r"((r)[21]),"=r"((r)[22]),"=r"((r)[23]),\
          "=r"((r)[24]),"=r"((r)[25]),"=r"((r)[26]),"=r"((r)[27]),"=r"((r)[28]),"=r"((r)[29]),\
          "=r"((r)[30]),"=r"((r)[31]) : "r"(ta))

// SW128 smem descriptor (LBO=1, SBO=64, layout=2, version=1)
#define DESC_BASE ((uint64_t(2) << 61) | (uint64_t(1) << 46) | (uint64_t(64) << 32) | (uint64_t(1) << 16))
__device__ __forceinline__ uint64_t make_desc(uint32_t saddr) {
    return DESC_BASE | ((uint64_t)(saddr >> 4) & 0x3FFF);
}
// idesc: F32 accum, BF16 a/b, N=128, M=128
#define MMA_IDESC 0x8200490u
#endif  // HAS_TC

// ---------------- CSR build ----------------
__global__ void hist_kernel(const int* __restrict__ tgt, int* __restrict__ cnt, int e)
{
    int i = blockIdx.x * blockDim.x + threadIdx.x;
    if (i < e) atomicAdd(&cnt[tgt[i]], 1);
}

__global__ __launch_bounds__(1024) void scan1_kernel(
    const int* __restrict__ cnt, int* __restrict__ rowptr, int* __restrict__ bsums, int n)
{
    __shared__ int wsum[32];
    int tid = threadIdx.x, lane = tid & 31, wid = tid >> 5;
    int i = blockIdx.x * 1024 + tid;
    int v = (i < n) ? cnt[i] : 0;
    int x = v;
    #pragma unroll
    for (int off = 1; off < 32; off <<= 1) {
        int y = __shfl_up_sync(0xffffffffu, x, off);
        if (lane >= off) x += y;
    }
    if (lane == 31) wsum[wid] = x;
    __syncthreads();
    if (wid == 0) {
        int ws = wsum[lane];
        #pragma unroll
        for (int off = 1; off < 32; off <<= 1) {
            int y = __shfl_up_sync(0xffffffffu, ws, off);
            if (lane >= off) ws += y;
        }
        wsum[lane] = ws;
    }
    __syncthreads();
    int excl = x - v + (wid ? wsum[wid - 1] : 0);
    if (i < n) rowptr[i] = excl;
    if (tid == 0) bsums[blockIdx.x] = wsum[31];
}

__global__ void scan2_kernel(int* __restrict__ bsums, int nb)
{
    __shared__ int w2[2];
    int tid = threadIdx.x, lane = tid & 31, wid = tid >> 5;
    int v = (tid < nb) ? bsums[tid] : 0;
    int x = v;
    #pragma unroll
    for (int off = 1; off < 32; off <<= 1) {
        int y = __shfl_up_sync(0xffffffffu, x, off);
        if (lane >= off) x += y;
    }
    if (lane == 31) w2[wid] = x;
    __syncthreads();
    int incl = x + (wid ? w2[0] : 0);
    if (tid < nb) bsums[tid] = incl - v;
    if (tid == 63) bsums[nb] = incl;
}

__global__ __launch_bounds__(1024) void scan3_kernel(
    int* __restrict__ rowptr, int* __restrict__ cursor,
    const int* __restrict__ bsums, int n, int nb)
{
    int i = blockIdx.x * 1024 + threadIdx.x;
    if (i < n) {
        int r = rowptr[i] + bsums[blockIdx.x];
        rowptr[i] = r;
        cursor[i] = r;
    }
    if (i == 0) rowptr[n] = bsums[nb];
}

__global__ void scatter_kernel(const int* __restrict__ src, const int* __restrict__ tgt,
                               const float* __restrict__ ew, int* __restrict__ cursor,
                               int2* __restrict__ epack, int e)
{
    int i = blockIdx.x * blockDim.x + threadIdx.x;
    if (i < e) {
        int t = tgt[i];
        int pos = atomicAdd(&cursor[t], 1);
        epack[pos] = make_int2(src[i], __float_as_int(ew[i]));
    }
}

// ---------------- prep: W^T -> swizzled bf16 hi/lo images + fused bias ----------------
// W is [129][DIM] row-major. B image row n, col k holds W[k+1][n].
__global__ void prep_kernel(const float* __restrict__ W, const float* __restrict__ bvec,
                            const float* __restrict__ tptr,
                            char* __restrict__ bhi, char* __restrict__ blo,
                            float* __restrict__ bias)
{
    int tid = threadIdx.x;
    for (int idx = tid; idx < DIM * DIM; idx += blockDim.x) {
        int n = idx & (DIM - 1);
        int k = idx >> 7;
        float w = W[(k + 1) * DIM + n];
        __nv_bfloat16 h = __float2bfloat16(w);
        __nv_bfloat16 l = __float2bfloat16(w - __bfloat162float(h));
        uint32_t so = sw_off(n, k);
        *(__nv_bfloat16*)(bhi + so) = h;
        *(__nv_bfloat16*)(blo + so) = l;
    }
    if (tid < DIM) bias[tid] = bvec[tid] + (*tptr) * W[tid];
}

// ---------------- tcgen05 split-bf16 GEMM: S = X @ W + bias ----------------
// smem layout
#define OFF_TMEM 0
#define OFF_MBAR 8
#define OFF_BIAS 16
#define OFF_AHI  1024
#define OFF_ALO  (1024 + 32768)
#define OFF_BHI  (1024 + 65536)
#define OFF_BLO  (1024 + 98304)
#define SMEM_TOT (1024 + 131072)

__global__ __launch_bounds__(256, 1) void mma_gemm_kernel(
    const float* __restrict__ X, const char* __restrict__ btHi,
    const char* __restrict__ btLo, const float* __restrict__ bias,
    float* __restrict__ S, int n)
{
#if HAS_TC
    extern __shared__ char smem[];
    uint32_t sb = smem_u32(smem);
    int tid = threadIdx.x, wid = tid >> 5, lid = tid & 31;
    int block_row = blockIdx.x * 128;

    if (wid == 0) {
        TC_ALLOC(sb + OFF_TMEM, 128);
        TC_RELINQ();
    }
    if (tid == 0) MBAR_INIT(sb + OFF_MBAR, 1);

    // copy pre-swizzled B images (L2-resident): 2 x 2048 float4
    {
        const float4* s0 = (const float4*)btHi;
        const float4* s1 = (const float4*)btLo;
        float4* d0 = (float4*)(smem + OFF_BHI);
        float4* d1 = (float4*)(smem + OFF_BLO);
        #pragma unroll
        for (int j = 0; j < 8; j++) {
            int i = tid + j * 256;
            d0[i] = s0[i];
            d1[i] = s1[i];
        }
    }
    // load X tile, split to bf16 hi/lo, swizzle-store: 4096 float4, 16/thread
    {
        #pragma unroll
        for (int j = 0; j < 16; j++) {
            int i = tid + j * 256;
            int r  = i >> 5;
            int c4 = (i & 31) * 4;
            int grow = block_row + r;
            float4 v = make_float4(0.f, 0.f, 0.f, 0.f);
            if (grow < n) v = *(const float4*)(X + (size_t)grow * DIM + c4);
            __nv_bfloat16 h0 = __float2bfloat16(v.x), h1 = __float2bfloat16(v.y);
            __nv_bfloat16 h2 = __float2bfloat16(v.z), h3 = __float2bfloat16(v.w);
            __nv_bfloat16 l0 = __float2bfloat16(v.x - __bfloat162float(h0));
            __nv_bfloat16 l1 = __float2bfloat16(v.y - __bfloat162float(h1));
            __nv_bfloat16 l2 = __float2bfloat16(v.z - __bfloat162float(h2));
            __nv_bfloat16 l3 = __float2bfloat16(v.w - __bfloat162float(h3));
            uint2 hv, lv;
            hv.x = ((uint32_t)__bfloat16_as_ushort(h1) << 16) | __bfloat16_as_ushort(h0);
            hv.y = ((uint32_t)__bfloat16_as_ushort(h3) << 16) | __bfloat16_as_ushort(h2);
            lv.x = ((uint32_t)__bfloat16_as_ushort(l1) << 16) | __bfloat16_as_ushort(l0);
            lv.y = ((uint32_t)__bfloat16_as_ushort(l3) << 16) | __bfloat16_as_ushort(l2);
            uint32_t so = sw_off(r, c4);
            *(uint2*)(smem + OFF_AHI + so) = hv;
            *(uint2*)(smem + OFF_ALO + so) = lv;
        }
    }
    if (tid < DIM) ((float*)(smem + OFF_BIAS))[tid] = bias[tid];

    asm volatile("fence.proxy.async.shared::cta;" ::: "memory");
    __syncthreads();

    uint32_t tmem;
    asm volatile("ld.shared.b32 %0, [%1];" : "=r"(tmem) : "r"(sb + OFF_TMEM));

    if (wid == 0 && elect_one()) {
        uint64_t aB[2] = { make_desc(sb + OFF_AHI), make_desc(sb + OFF_ALO) };
        uint64_t bB[2] = { make_desc(sb + OFF_BHI), make_desc(sb + OFF_BLO) };
        const int pa[3] = {0, 0, 1};
        const int pb[3] = {0, 1, 0};
        #pragma unroll
        for (int p = 0; p < 3; p++) {
            #pragma unroll
            for (int k = 0; k < 8; k++) {
                uint64_t off = (k < 4) ? (uint64_t)(2 * k) : (uint64_t)(1024 + 2 * (k - 4));
                tc_mma_f16_ss(tmem, aB[pa[p]] + off, bB[pb[p]] + off, MMA_IDESC,
                              (p != 0 || k != 0) ? 1u : 0u);
            }
        }
        TC_COMMIT(sb + OFF_MBAR);
    }

    MBAR_WAIT(sb + OFF_MBAR, 0);
    TC_FENCE_AFTER();

    if (wid < 4) {
        int row = block_row + wid * 32 + lid;
        const float* bias_s = (const float*)(smem + OFF_BIAS);
        #pragma unroll
        for (int chunk = 0; chunk < 4; chunk++) {
            uint32_t r[32];
            TC_LD_X32(r, tmem + chunk * 32);
            TC_WAIT_LD();
            if (row < n) {
                #pragma unroll
                for (int jj = 0; jj < 32; jj += 4) {
                    float4 o;
                    o.x = __uint_as_float(r[jj + 0]) + bias_s[chunk * 32 + jj + 0];
                    o.y = __uint_as_float(r[jj + 1]) + bias_s[chunk * 32 + jj + 1];
                    o.z = __uint_as_float(r[jj + 2]) + bias_s[chunk * 32 + jj + 2];
                    o.w = __uint_as_float(r[jj + 3]) + bias_s[chunk * 32 + jj + 3];
                    *(float4*)(S + (size_t)row * DIM + chunk * 32 + jj) = o;
                }
            }
        }
        TC_FENCE_BEFORE();
    }

    __syncthreads();
    if (tid == 0) MBAR_INVAL(sb + OFF_MBAR);
    __syncthreads();
    if (wid == 0) TC_DEALLOC(tmem, 128);
#else
    // Functional fallback for the compatibility-PTX pass (compute_103 without
    // accelerated features). Never executed on GB300 — the sm_103a cubin runs.
    int tid = threadIdx.x;
    int block_row = blockIdx.x * 128;
    for (int e = tid; e < 128 * DIM; e += blockDim.x) {
        int r = e >> 7, c = e & (DIM - 1);
        int grow = block_row + r;
        if (grow < n) {
            float acc = bias[c];
            for (int k = 0; k < DIM; k++) {
                uint32_t so = sw_off(c, k);
                float w = __bfloat162float(*(const __nv_bfloat16*)(btHi + so))
                        + __bfloat162float(*(const __nv_bfloat16*)(btLo + so));
                acc = fmaf(X[(size_t)grow * DIM + k], w, acc);
            }
            S[(size_t)grow * DIM + c] = acc;
        }
    }
#endif
}

// ---------------- aggregation + ReLU + GroupNorm (group size 4 == one lane) ----------------
__global__ __launch_bounds__(256) void agg_gn_kernel(
    const float* __restrict__ S, const int* __restrict__ rowptr,
    const int2* __restrict__ epack,
    const float* __restrict__ gamma, const float* __restrict__ beta,
    float* __restrict__ out, int n)
{
    int warp = (blockIdx.x * blockDim.x + threadIdx.x) >> 5;
    int lane = threadIdx.x & 31;
    if (warp >= n) return;

    int beg = rowptr[warp];
    int end = rowptr[warp + 1];

    float ax = 0.f, ay = 0.f, az = 0.f, aw = 0.f;
    for (int j = beg; j < end; j++) {
        int2 ep = epack[j];
        float w = __int_as_float(ep.y);
        float4 v = *(const float4*)(S + (size_t)ep.x * DIM + lane * 4);
        ax = fmaf(w, v.x, ax);
        ay = fmaf(w, v.y, ay);
        az = fmaf(w, v.z, az);
        aw = fmaf(w, v.w, aw);
    }
    ax = fmaxf(ax, 0.f); ay = fmaxf(ay, 0.f);
    az = fmaxf(az, 0.f); aw = fmaxf(aw, 0.f);
    float mu = (ax + ay + az + aw) * 0.25f;
    float d0 = ax - mu, d1 = ay - mu, d2 = az - mu, d3 = aw - mu;
    float var = (d0 * d0 + d1 * d1 + d2 * d2 + d3 * d3) * 0.25f;
    float inv = rsqrtf(var + EPS);
    float4 g = *(const float4*)(gamma + lane * 4);
    float4 b = *(const float4*)(beta  + lane * 4);
    float4 o;
    o.x = fmaf(d0 * inv, g.x, b.x);
    o.y = fmaf(d1 * inv, g.y, b.y);
    o.z = fmaf(d2 * inv, g.z, b.z);
    o.w = fmaf(d3 * inv, g.w, b.w);
    *(float4*)(out + (size_t)warp * DIM + lane * 4) = o;
}

// ---------------- launch ----------------
extern "C" void kernel_launch(void* const* d_in, const int* in_sizes, int n_in,
                              void* d_out, int out_size)
{
    const float* t      = (const float*)d_in[0];
    const float* x      = (const float*)d_in[1];
    const int*   src    = (const int*)  d_in[2];
    const int*   tgt    = (const int*)  d_in[3];
    const float* edge_w = (const float*)d_in[4];
    const float* W1     = (const float*)d_in[5];
    const float* b1     = (const float*)d_in[6];
    const float* W2     = (const float*)d_in[7];
    const float* b2     = (const float*)d_in[8];
    const float* gamma1 = (const float*)d_in[9];
    const float* beta1  = (const float*)d_in[10];
    const float* gamma2 = (const float*)d_in[11];
    const float* beta2  = (const float*)d_in[12];
    float* out = (float*)d_out;

    float* s_buf;  cudaGetSymbolAddress((void**)&s_buf,  g_s);
    float* h_buf;  cudaGetSymbolAddress((void**)&h_buf,  g_h);
    int*   cnt;    cudaGetSymbolAddress((void**)&cnt,    g_cnt);
    int*   rowptr; cudaGetSymbolAddress((void**)&rowptr, g_rowptr);
    int*   cursor; cudaGetSymbolAddress((void**)&cursor, g_cursor);
    int2*  epack;  cudaGetSymbolAddress((void**)&epack,  g_epack);
    int*   bsums;  cudaGetSymbolAddress((void**)&bsums,  g_bsums);
    char*  bt_hi;  cudaGetSymbolAddress((void**)&bt_hi,  g_bt_hi);
    char*  bt_lo;  cudaGetSymbolAddress((void**)&bt_lo,  g_bt_lo);
    float* bias;   cudaGetSymbolAddress((void**)&bias,   g_bias);

    cudaFuncSetAttribute(mma_gemm_kernel,
                         cudaFuncAttributeMaxDynamicSharedMemorySize, SMEM_TOT);

    // ---- CSR build + weight prep (independent; reused by both layers) ----
    cudaMemsetAsync(cnt, 0, N_NODES * sizeof(int));
    prep_kernel<<<1, 256>>>(W1, b1, t, bt_hi,         bt_lo,         bias);
    prep_kernel<<<1, 256>>>(W2, b2, t, bt_hi + 32768, bt_lo + 32768, bias + DIM);
    hist_kernel<<<(N_EDGES + 255) / 256, 256>>>(tgt, cnt, N_EDGES);
    scan1_kernel<<<N_SBLOCKS, 1024>>>(cnt, rowptr, bsums, N_NODES);
    scan2_kernel<<<1, 64>>>(bsums, N_SBLOCKS);
    scan3_kernel<<<N_SBLOCKS, 1024>>>(rowptr, cursor, bsums, N_NODES, N_SBLOCKS);
    scatter_kernel<<<(N_EDGES + 255) / 256, 256>>>(src, tgt, edge_w, cursor, epack, N_EDGES);

    int agg_blocks = (N_NODES + 7) / 8;

    // ---- layer 1 ----
    mma_gemm_kernel<<<N_TILES, 256, SMEM_TOT>>>(x, bt_hi, bt_lo, bias, s_buf, N_NODES);
    agg_gn_kernel<<<agg_blocks, 256>>>(s_buf, rowptr, epack, gamma1, beta1, h_buf, N_NODES);

    // ---- layer 2 ----
    mma_gemm_kernel<<<N_TILES, 256, SMEM_TOT>>>(h_buf, bt_hi + 32768, bt_lo + 32768,
                                                bias + DIM, s_buf, N_NODES);
    agg_gn_kernel<<<agg_blocks, 256>>>(s_buf, rowptr, epack, gamma2, beta2, out, N_NODES);
}

// round 6
// speedup vs baseline: 1.7093x; 1.5874x over previous
#include <cuda_runtime.h>
#include <cuda_bf16.h>
#include <cstdint>

#define N_NODES 50000
#define N_EDGES 600000
#define DIM 128
#define EPS 1e-5f
#define N_SBLOCKS ((N_NODES + 1023) / 1024)   // 49
#define N_TILES ((N_NODES + 127) / 128)       // 391

#if defined(__CUDA_ARCH__) && defined(__CUDA_ARCH_FEAT_SM103_ALL)
#define HAS_TC 1
#else
#define HAS_TC 0
#endif

// ---------------- scratch (device globals; no allocation allowed) ----------------
__device__ __align__(16) float g_s[N_NODES * DIM];
__device__ __align__(16) float g_h[N_NODES * DIM];
__device__ int   g_cnt[N_NODES];
__device__ int   g_rowptr[N_NODES + 1];
__device__ int   g_cursor[N_NODES];
__device__ int2  g_epack[N_EDGES];
__device__ int   g_bsums[N_SBLOCKS + 1];
// pre-swizzled W^T bf16 SMEM images (32KB each) + fused bias, per layer
__device__ __align__(16) char  g_bt_hi[2][32768];
__device__ __align__(16) char  g_bt_lo[2][32768];
__device__ __align__(16) float g_bias[2][DIM];

// blocked-atom SW128 byte offset for [128 rows x 128 bf16 cols]
__host__ __device__ __forceinline__ uint32_t sw_off(int r, int c) {
    uint32_t off = (uint32_t)((r >> 3) + (c >> 6) * 16) * 1024u + (uint32_t)(r & 7) * 128u
                 + (uint32_t)(c & 63) * 2u;
    return off ^ ((off >> 3) & 0x70);
}

// ---------------- PTX helpers (used only under HAS_TC) ----------------
__device__ __forceinline__ uint32_t smem_u32(const void* p) {
    uint32_t a;
    asm("{ .reg .u64 t; cvta.to.shared.u64 t, %1; cvt.u32.u64 %0, t; }" : "=r"(a) : "l"(p));
    return a;
}
#if HAS_TC
__device__ __forceinline__ uint32_t elect_one() {
    uint32_t p;
    asm volatile("{ .reg .pred p; elect.sync _|p, 0xFFFFFFFF; selp.b32 %0, 1, 0, p; }" : "=r"(p));
    return p;
}
#define MBAR_INIT(a, c) asm volatile("mbarrier.init.shared.b64 [%0], %1;" :: "r"(a), "r"(c) : "memory")
#define MBAR_INVAL(a)   asm volatile("mbarrier.inval.shared.b64 [%0];" :: "r"(a) : "memory")
#define MBAR_WAIT(a, ph) do {                                                              \
    uint32_t _m = (a), _p = (ph), _d;                                                      \
    asm volatile("{ .reg .pred p; mbarrier.try_wait.parity.acquire.cta.shared::cta.b64 p, [%1], %2;" \
                 " selp.b32 %0, 1, 0, p; }" : "=r"(_d) : "r"(_m), "r"(_p) : "memory");     \
    if (!_d) {                                                                             \
        asm volatile("{ .reg .pred P1; WL%=: mbarrier.try_wait.parity.acquire.cta.shared::cta.b64 P1, [%0], %1, 0x989680;" \
                     " @P1 bra.uni WD%=; bra.uni WL%=; WD%=: }" :: "r"(_m), "r"(_p) : "memory"); \
    } } while (0)
#define TC_ALLOC(sa, nc)  asm volatile("tcgen05.alloc.cta_group::1.sync.aligned.shared::cta.b32 [%0], %1;" :: "r"(sa), "r"(nc) : "memory")
#define TC_RELINQ()       asm volatile("tcgen05.relinquish_alloc_permit.cta_group::1.sync.aligned;")
#define TC_DEALLOC(t, nc) asm volatile("tcgen05.dealloc.cta_group::1.sync.aligned.b32 %0, %1;" :: "r"(t), "r"(nc))
#define TC_COMMIT(mb)     asm volatile("tcgen05.commit.cta_group::1.mbarrier::arrive::one.shared::cluster.b64 [%0];" :: "r"(mb) : "memory")
#define TC_FENCE_AFTER()  asm volatile("tcgen05.fence::after_thread_sync;" ::: "memory")
#define TC_FENCE_BEFORE() asm volatile("tcgen05.fence::before_thread_sync;" ::: "memory")
#define TC_WAIT_LD()      asm volatile("tcgen05.wait::ld.sync.aligned;" ::: "memory")

__device__ __forceinline__ void tc_mma_f16_ss(uint32_t d, uint64_t ad, uint64_t bd,
                                              uint32_t idesc, uint32_t en) {
    asm volatile("{ .reg .pred p; setp.ne.u32 p, %5, 0;"
                 " tcgen05.mma.cta_group::1.kind::f16 [%0], %1, %2, %3, {%4, %4, %4, %4}, p; }"
                 :: "r"(d), "l"(ad), "l"(bd), "r"(idesc), "r"(0u), "r"(en) : "memory");
}
#define TC_LD_X32(r, ta)                                                                   \
    asm volatile("tcgen05.ld.sync.aligned.32x32b.x32.b32 "                                 \
        "{%0,%1,%2,%3,%4,%5,%6,%7,%8,%9,%10,%11,%12,%13,%14,%15,"                          \
        "%16,%17,%18,%19,%20,%21,%22,%23,%24,%25,%26,%27,%28,%29,%30,%31}, [%32];"         \
        : "=r"((r)[0]),"=r"((r)[1]),"=r"((r)[2]),"=r"((r)[3]),"=r"((r)[4]),"=r"((r)[5]),   \
          "=r"((r)[6]),"=r"((r)[7]),"=r"((r)[8]),"=r"((r)[9]),"=r"((r)[10]),"=r"((r)[11]), \
          "=r"((r)[12]),"=r"((r)[13]),"=r"((r)[14]),"=r"((r)[15]),"=r"((r)[16]),"=r"((r)[17]),\
          "=r"((r)[18]),"=r"((r)[19]),"=r"((r)[20]),"=r"((r)[21]),"=r"((r)[22]),"=r"((r)[23]),\
          "=r"((r)[24]),"=r"((r)[25]),"=r"((r)[26]),"=r"((r)[27]),"=r"((r)[28]),"=r"((r)[29]),\
          "=r"((r)[30]),"=r"((r)[31]) : "r"(ta))

// SW128 smem descriptor (LBO=1, SBO=64, layout=2, version=1)
#define DESC_BASE ((uint64_t(2) << 61) | (uint64_t(1) << 46) | (uint64_t(64) << 32) | (uint64_t(1) << 16))
__device__ __forceinline__ uint64_t make_desc(uint32_t saddr) {
    return DESC_BASE | ((uint64_t)(saddr >> 4) & 0x3FFF);
}
// idesc: F32 accum, BF16 a/b, N=128, M=128
#define MMA_IDESC 0x8200490u
#endif  // HAS_TC

// ---------------- CSR build ----------------
__global__ void hist_kernel(const int* __restrict__ tgt, int* __restrict__ cnt, int e)
{
    int i = blockIdx.x * blockDim.x + threadIdx.x;
    if (i < e) atomicAdd(&cnt[tgt[i]], 1);
}

__global__ __launch_bounds__(1024) void scan1_kernel(
    const int* __restrict__ cnt, int* __restrict__ rowptr, int* __restrict__ bsums, int n)
{
    __shared__ int wsum[32];
    int tid = threadIdx.x, lane = tid & 31, wid = tid >> 5;
    int i = blockIdx.x * 1024 + tid;
    int v = (i < n) ? cnt[i] : 0;
    int x = v;
    #pragma unroll
    for (int off = 1; off < 32; off <<= 1) {
        int y = __shfl_up_sync(0xffffffffu, x, off);
        if (lane >= off) x += y;
    }
    if (lane == 31) wsum[wid] = x;
    __syncthreads();
    if (wid == 0) {
        int ws = wsum[lane];
        #pragma unroll
        for (int off = 1; off < 32; off <<= 1) {
            int y = __shfl_up_sync(0xffffffffu, ws, off);
            if (lane >= off) ws += y;
        }
        wsum[lane] = ws;
    }
    __syncthreads();
    int excl = x - v + (wid ? wsum[wid - 1] : 0);
    if (i < n) rowptr[i] = excl;
    if (tid == 0) bsums[blockIdx.x] = wsum[31];
}

__global__ void scan2_kernel(int* __restrict__ bsums, int nb)
{
    __shared__ int w2[2];
    int tid = threadIdx.x, lane = tid & 31, wid = tid >> 5;
    int v = (tid < nb) ? bsums[tid] : 0;
    int x = v;
    #pragma unroll
    for (int off = 1; off < 32; off <<= 1) {
        int y = __shfl_up_sync(0xffffffffu, x, off);
        if (lane >= off) x += y;
    }
    if (lane == 31) w2[wid] = x;
    __syncthreads();
    int incl = x + (wid ? w2[0] : 0);
    if (tid < nb) bsums[tid] = incl - v;
    if (tid == 63) bsums[nb] = incl;
}

__global__ __launch_bounds__(1024) void scan3_kernel(
    int* __restrict__ rowptr, int* __restrict__ cursor,
    const int* __restrict__ bsums, int n, int nb)
{
    int i = blockIdx.x * 1024 + threadIdx.x;
    if (i < n) {
        int r = rowptr[i] + bsums[blockIdx.x];
        rowptr[i] = r;
        cursor[i] = r;
    }
    if (i == 0) rowptr[n] = bsums[nb];
}

__global__ void scatter_kernel(const int* __restrict__ src, const int* __restrict__ tgt,
                               const float* __restrict__ ew, int* __restrict__ cursor,
                               int2* __restrict__ epack, int e)
{
    int i = blockIdx.x * blockDim.x + threadIdx.x;
    if (i < e) {
        int t = tgt[i];
        int pos = atomicAdd(&cursor[t], 1);
        epack[pos] = make_int2(src[i], __float_as_int(ew[i]));
    }
}

// ---------------- prep: W^T -> swizzled bf16 hi/lo images + fused bias ----------------
// W is [129][DIM] row-major. B image row n, col k holds W[k+1][n].
// Parallel: one thread per 16B chunk (8 consecutive k of one row n). Within an
// 8k-aligned chunk the SW128 XOR is constant -> single uint4 store per image.
__global__ void prep_kernel(const float* __restrict__ W, const float* __restrict__ bvec,
                            const float* __restrict__ tptr,
                            char* __restrict__ bhi, char* __restrict__ blo,
                            float* __restrict__ bias)
{
    int chunk = blockIdx.x * blockDim.x + threadIdx.x;   // 0..2047
    if (chunk < 2048) {
        int n  = chunk >> 4;          // row 0..127
        int k8 = (chunk & 15) * 8;    // k base, multiple of 8
        uint32_t hp[4], lp[4];
        #pragma unroll
        for (int j = 0; j < 4; j++) {
            float w0 = W[(k8 + 2 * j + 1) * DIM + n];
            float w1 = W[(k8 + 2 * j + 2) * DIM + n];
            __nv_bfloat16 h0 = __float2bfloat16(w0);
            __nv_bfloat16 h1 = __float2bfloat16(w1);
            __nv_bfloat16 l0 = __float2bfloat16(w0 - __bfloat162float(h0));
            __nv_bfloat16 l1 = __float2bfloat16(w1 - __bfloat162float(h1));
            hp[j] = ((uint32_t)__bfloat16_as_ushort(h1) << 16) | __bfloat16_as_ushort(h0);
            lp[j] = ((uint32_t)__bfloat16_as_ushort(l1) << 16) | __bfloat16_as_ushort(l0);
        }
        uint32_t so = sw_off(n, k8);   // 16B-aligned, swizzle constant over the chunk
        *(uint4*)(bhi + so) = make_uint4(hp[0], hp[1], hp[2], hp[3]);
        *(uint4*)(blo + so) = make_uint4(lp[0], lp[1], lp[2], lp[3]);
    }
    if (blockIdx.x == 0 && threadIdx.x < DIM)
        bias[threadIdx.x] = bvec[threadIdx.x] + (*tptr) * W[threadIdx.x];
}

// ---------------- tcgen05 split-bf16 GEMM: S = X @ W + bias ----------------
// smem layout
#define OFF_TMEM 0
#define OFF_MBAR 8
#define OFF_BIAS 16
#define OFF_AHI  1024
#define OFF_ALO  (1024 + 32768)
#define OFF_BHI  (1024 + 65536)
#define OFF_BLO  (1024 + 98304)
#define SMEM_TOT (1024 + 131072)

__global__ __launch_bounds__(256, 1) void mma_gemm_kernel(
    const float* __restrict__ X, const char* __restrict__ btHi,
    const char* __restrict__ btLo, const float* __restrict__ bias,
    float* __restrict__ S, int n)
{
#if HAS_TC
    extern __shared__ char smem[];
    uint32_t sb = smem_u32(smem);
    int tid = threadIdx.x, wid = tid >> 5, lid = tid & 31;
    int block_row = blockIdx.x * 128;

    if (wid == 0) {
        TC_ALLOC(sb + OFF_TMEM, 128);
        TC_RELINQ();
    }
    if (tid == 0) MBAR_INIT(sb + OFF_MBAR, 1);

    // copy pre-swizzled B images (L2-resident): 2 x 2048 float4
    {
        const float4* s0 = (const float4*)btHi;
        const float4* s1 = (const float4*)btLo;
        float4* d0 = (float4*)(smem + OFF_BHI);
        float4* d1 = (float4*)(smem + OFF_BLO);
        #pragma unroll
        for (int j = 0; j < 8; j++) {
            int i = tid + j * 256;
            d0[i] = s0[i];
            d1[i] = s1[i];
        }
    }
    // load X tile, split to bf16 hi/lo, swizzle-store: 4096 float4, 16/thread
    {
        #pragma unroll
        for (int j = 0; j < 16; j++) {
            int i = tid + j * 256;
            int r  = i >> 5;
            int c4 = (i & 31) * 4;
            int grow = block_row + r;
            float4 v = make_float4(0.f, 0.f, 0.f, 0.f);
            if (grow < n) v = *(const float4*)(X + (size_t)grow * DIM + c4);
            __nv_bfloat16 h0 = __float2bfloat16(v.x), h1 = __float2bfloat16(v.y);
            __nv_bfloat16 h2 = __float2bfloat16(v.z), h3 = __float2bfloat16(v.w);
            __nv_bfloat16 l0 = __float2bfloat16(v.x - __bfloat162float(h0));
            __nv_bfloat16 l1 = __float2bfloat16(v.y - __bfloat162float(h1));
            __nv_bfloat16 l2 = __float2bfloat16(v.z - __bfloat162float(h2));
            __nv_bfloat16 l3 = __float2bfloat16(v.w - __bfloat162float(h3));
            uint2 hv, lv;
            hv.x = ((uint32_t)__bfloat16_as_ushort(h1) << 16) | __bfloat16_as_ushort(h0);
            hv.y = ((uint32_t)__bfloat16_as_ushort(h3) << 16) | __bfloat16_as_ushort(h2);
            lv.x = ((uint32_t)__bfloat16_as_ushort(l1) << 16) | __bfloat16_as_ushort(l0);
            lv.y = ((uint32_t)__bfloat16_as_ushort(l3) << 16) | __bfloat16_as_ushort(l2);
            uint32_t so = sw_off(r, c4);
            *(uint2*)(smem + OFF_AHI + so) = hv;
            *(uint2*)(smem + OFF_ALO + so) = lv;
        }
    }
    if (tid < DIM) ((float*)(smem + OFF_BIAS))[tid] = bias[tid];

    asm volatile("fence.proxy.async.shared::cta;" ::: "memory");
    __syncthreads();

    uint32_t tmem;
    asm volatile("ld.shared.b32 %0, [%1];" : "=r"(tmem) : "r"(sb + OFF_TMEM));

    if (wid == 0 && elect_one()) {
        uint64_t aB[2] = { make_desc(sb + OFF_AHI), make_desc(sb + OFF_ALO) };
        uint64_t bB[2] = { make_desc(sb + OFF_BHI), make_desc(sb + OFF_BLO) };
        const int pa[3] = {0, 0, 1};
        const int pb[3] = {0, 1, 0};
        #pragma unroll
        for (int p = 0; p < 3; p++) {
            #pragma unroll
            for (int k = 0; k < 8; k++) {
                uint64_t off = (k < 4) ? (uint64_t)(2 * k) : (uint64_t)(1024 + 2 * (k - 4));
                tc_mma_f16_ss(tmem, aB[pa[p]] + off, bB[pb[p]] + off, MMA_IDESC,
                              (p != 0 || k != 0) ? 1u : 0u);
            }
        }
        TC_COMMIT(sb + OFF_MBAR);
    }

    MBAR_WAIT(sb + OFF_MBAR, 0);
    TC_FENCE_AFTER();

    if (wid < 4) {
        int row = block_row + wid * 32 + lid;
        const float* bias_s = (const float*)(smem + OFF_BIAS);
        #pragma unroll
        for (int chunk = 0; chunk < 4; chunk++) {
            uint32_t r[32];
            TC_LD_X32(r, tmem + chunk * 32);
            TC_WAIT_LD();
            if (row < n) {
                #pragma unroll
                for (int jj = 0; jj < 32; jj += 4) {
                    float4 o;
                    o.x = __uint_as_float(r[jj + 0]) + bias_s[chunk * 32 + jj + 0];
                    o.y = __uint_as_float(r[jj + 1]) + bias_s[chunk * 32 + jj + 1];
                    o.z = __uint_as_float(r[jj + 2]) + bias_s[chunk * 32 + jj + 2];
                    o.w = __uint_as_float(r[jj + 3]) + bias_s[chunk * 32 + jj + 3];
                    *(float4*)(S + (size_t)row * DIM + chunk * 32 + jj) = o;
                }
            }
        }
        TC_FENCE_BEFORE();
    }

    __syncthreads();
    if (tid == 0) MBAR_INVAL(sb + OFF_MBAR);
    __syncthreads();
    if (wid == 0) TC_DEALLOC(tmem, 128);
#else
    // Functional fallback for the compatibility-PTX pass (compute_103 without
    // accelerated features). Never executed on GB300 — the sm_103a cubin runs.
    int tid = threadIdx.x;
    int block_row = blockIdx.x * 128;
    for (int e = tid; e < 128 * DIM; e += blockDim.x) {
        int r = e >> 7, c = e & (DIM - 1);
        int grow = block_row + r;
        if (grow < n) {
            float acc = bias[c];
            for (int k = 0; k < DIM; k++) {
                uint32_t so = sw_off(c, k);
                float w = __bfloat162float(*(const __nv_bfloat16*)(btHi + so))
                        + __bfloat162float(*(const __nv_bfloat16*)(btLo + so));
                acc = fmaf(X[(size_t)grow * DIM + k], w, acc);
            }
            S[(size_t)grow * DIM + c] = acc;
        }
    }
#endif
}

// ---------------- aggregation + ReLU + GroupNorm (group size 4 == one lane) ----------------
__global__ __launch_bounds__(256) void agg_gn_kernel(
    const float* __restrict__ S, const int* __restrict__ rowptr,
    const int2* __restrict__ epack,
    const float* __restrict__ gamma, const float* __restrict__ beta,
    float* __restrict__ out, int n)
{
    int warp = (blockIdx.x * blockDim.x + threadIdx.x) >> 5;
    int lane = threadIdx.x & 31;
    if (warp >= n) return;

    int beg = rowptr[warp];
    int end = rowptr[warp + 1];

    float ax = 0.f, ay = 0.f, az = 0.f, aw = 0.f;
    int j = beg;
    for (; j + 4 <= end; j += 4) {
        int2 e0 = epack[j + 0];
        int2 e1 = epack[j + 1];
        int2 e2 = epack[j + 2];
        int2 e3 = epack[j + 3];
        float4 v0 = *(const float4*)(S + (size_t)e0.x * DIM + lane * 4);
        float4 v1 = *(const float4*)(S + (size_t)e1.x * DIM + lane * 4);
        float4 v2 = *(const float4*)(S + (size_t)e2.x * DIM + lane * 4);
        float4 v3 = *(const float4*)(S + (size_t)e3.x * DIM + lane * 4);
        float w0 = __int_as_float(e0.y), w1 = __int_as_float(e1.y);
        float w2 = __int_as_float(e2.y), w3 = __int_as_float(e3.y);
        ax = fmaf(w0, v0.x, ax); ay = fmaf(w0, v0.y, ay);
        az = fmaf(w0, v0.z, az); aw = fmaf(w0, v0.w, aw);
        ax = fmaf(w1, v1.x, ax); ay = fmaf(w1, v1.y, ay);
        az = fmaf(w1, v1.z, az); aw = fmaf(w1, v1.w, aw);
        ax = fmaf(w2, v2.x, ax); ay = fmaf(w2, v2.y, ay);
        az = fmaf(w2, v2.z, az); aw = fmaf(w2, v2.w, aw);
        ax = fmaf(w3, v3.x, ax); ay = fmaf(w3, v3.y, ay);
        az = fmaf(w3, v3.z, az); aw = fmaf(w3, v3.w, aw);
    }
    for (; j < end; j++) {
        int2 ep = epack[j];
        float w = __int_as_float(ep.y);
        float4 v = *(const float4*)(S + (size_t)ep.x * DIM + lane * 4);
        ax = fmaf(w, v.x, ax); ay = fmaf(w, v.y, ay);
        az = fmaf(w, v.z, az); aw = fmaf(w, v.w, aw);
    }
    ax = fmaxf(ax, 0.f); ay = fmaxf(ay, 0.f);
    az = fmaxf(az, 0.f); aw = fmaxf(aw, 0.f);
    float mu = (ax + ay + az + aw) * 0.25f;
    float d0 = ax - mu, d1 = ay - mu, d2 = az - mu, d3 = aw - mu;
    float var = (d0 * d0 + d1 * d1 + d2 * d2 + d3 * d3) * 0.25f;
    float inv = rsqrtf(var + EPS);
    float4 g = *(const float4*)(gamma + lane * 4);
    float4 b = *(const float4*)(beta  + lane * 4);
    float4 o;
    o.x = fmaf(d0 * inv, g.x, b.x);
    o.y = fmaf(d1 * inv, g.y, b.y);
    o.z = fmaf(d2 * inv, g.z, b.z);
    o.w = fmaf(d3 * inv, g.w, b.w);
    *(float4*)(out + (size_t)warp * DIM + lane * 4) = o;
}

// ---------------- launch ----------------
extern "C" void kernel_launch(void* const* d_in, const int* in_sizes, int n_in,
                              void* d_out, int out_size)
{
    const float* t      = (const float*)d_in[0];
    const float* x      = (const float*)d_in[1];
    const int*   src    = (const int*)  d_in[2];
    const int*   tgt    = (const int*)  d_in[3];
    const float* edge_w = (const float*)d_in[4];
    const float* W1     = (const float*)d_in[5];
    const float* b1     = (const float*)d_in[6];
    const float* W2     = (const float*)d_in[7];
    const float* b2     = (const float*)d_in[8];
    const float* gamma1 = (const float*)d_in[9];
    const float* beta1  = (const float*)d_in[10];
    const float* gamma2 = (const float*)d_in[11];
    const float* beta2  = (const float*)d_in[12];
    float* out = (float*)d_out;

    float* s_buf;  cudaGetSymbolAddress((void**)&s_buf,  g_s);
    float* h_buf;  cudaGetSymbolAddress((void**)&h_buf,  g_h);
    int*   cnt;    cudaGetSymbolAddress((void**)&cnt,    g_cnt);
    int*   rowptr; cudaGetSymbolAddress((void**)&rowptr, g_rowptr);
    int*   cursor; cudaGetSymbolAddress((void**)&cursor, g_cursor);
    int2*  epack;  cudaGetSymbolAddress((void**)&epack,  g_epack);
    int*   bsums;  cudaGetSymbolAddress((void**)&bsums,  g_bsums);
    char*  bt_hi;  cudaGetSymbolAddress((void**)&bt_hi,  g_bt_hi);
    char*  bt_lo;  cudaGetSymbolAddress((void**)&bt_lo,  g_bt_lo);
    float* bias;   cudaGetSymbolAddress((void**)&bias,   g_bias);

    cudaFuncSetAttribute(mma_gemm_kernel,
                         cudaFuncAttributeMaxDynamicSharedMemorySize, SMEM_TOT);

    int agg_blocks = (N_NODES + 7) / 8;

    // Launch order chosen so gemm1 is the 5th launch (ncu capture slot).
    cudaMemsetAsync(cnt, 0, N_NODES * sizeof(int));                                   // 0
    prep_kernel<<<8, 256>>>(W1, b1, t, bt_hi,         bt_lo,         bias);           // 1
    prep_kernel<<<8, 256>>>(W2, b2, t, bt_hi + 32768, bt_lo + 32768, bias + DIM);     // 2
    hist_kernel<<<(N_EDGES + 255) / 256, 256>>>(tgt, cnt, N_EDGES);                   // 3
    mma_gemm_kernel<<<N_TILES, 256, SMEM_TOT>>>(x, bt_hi, bt_lo, bias, s_buf, N_NODES); // 4 <- profiled
    scan1_kernel<<<N_SBLOCKS, 1024>>>(cnt, rowptr, bsums, N_NODES);                   // 5
    scan2_kernel<<<1, 64>>>(bsums, N_SBLOCKS);                                        // 6
    scan3_kernel<<<N_SBLOCKS, 1024>>>(rowptr, cursor, bsums, N_NODES, N_SBLOCKS);     // 7
    scatter_kernel<<<(N_EDGES + 255) / 256, 256>>>(src, tgt, edge_w, cursor, epack, N_EDGES); // 8

    // ---- layer 1 aggregation, then layer 2 ----
    agg_gn_kernel<<<agg_blocks, 256>>>(s_buf, rowptr, epack, gamma1, beta1, h_buf, N_NODES);
    mma_gemm_kernel<<<N_TILES, 256, SMEM_TOT>>>(h_buf, bt_hi + 32768, bt_lo + 32768,
                                                bias + DIM, s_buf, N_NODES);
    agg_gn_kernel<<<agg_blocks, 256>>>(s_buf, rowptr, epack, gamma2, beta2, out, N_NODES);
}